// round 1
// baseline (speedup 1.0000x reference)
#include <cuda_runtime.h>
#include <math.h>

#define B_   4096
#define INF  64
#define KM   16
#define SQ   32
#define HH   64
#define NMD  48
#define NH   512
#define NT   1024
#define PMAXF 8.0f

// Scratch (no allocations allowed)
__device__ float g_tab[KM * NT];   // G_k(p) tables
__device__ float g_mono[B_];       // mono_term per row

// ---------------------------------------------------------------------------
// Kernel 1: tabulate G_k(p) = softplus(mw3_k . tanh(mw2_k^T tanh(p*mw1_k+mb1_k)+mb2_k)+mb3_k)
// 64 blocks (4 per k) x 256 threads, one table entry per thread.
// ---------------------------------------------------------------------------
__global__ void __launch_bounds__(256) build_tab_kernel(
    const float* __restrict__ mw1, const float* __restrict__ mb1,
    const float* __restrict__ mw2, const float* __restrict__ mb2,
    const float* __restrict__ mw3, const float* __restrict__ mb3)
{
    __shared__ float s_w2[HH * HH];
    __shared__ float s_w1[HH], s_b1[HH], s_b2[HH], s_w3[HH];

    int k   = blockIdx.x >> 2;
    int sub = blockIdx.x & 3;

    for (int idx = threadIdx.x; idx < HH * HH; idx += blockDim.x)
        s_w2[idx] = mw2[k * HH * HH + idx];
    if (threadIdx.x < HH) {
        s_w1[threadIdx.x] = mw1[k * HH + threadIdx.x];
        s_b1[threadIdx.x] = mb1[k * HH + threadIdx.x];
        s_b2[threadIdx.x] = mb2[k * HH + threadIdx.x];
        s_w3[threadIdx.x] = mw3[k * HH + threadIdx.x];
    }
    __syncthreads();

    int i   = sub * 256 + threadIdx.x;      // 0..NT-1
    float p = -PMAXF + (2.f * PMAXF / (NT - 1)) * (float)i;

    float h1v[HH];
#pragma unroll
    for (int h = 0; h < HH; h++)
        h1v[h] = tanhf(fmaf(p, s_w1[h], s_b1[h]));

    float z = __ldg(mb3 + k);
#pragma unroll 4
    for (int j = 0; j < HH; j++) {
        float acc = s_b2[j];
#pragma unroll
        for (int h = 0; h < HH; h++)
            acc = fmaf(h1v[h], s_w2[h * HH + j], acc);
        z = fmaf(s_w3[j], tanhf(acc), z);
    }
    // softplus, numerically stable
    float g = fmaxf(z, 0.f) + log1pf(expf(-fabsf(z)));
    g_tab[k * NT + i] = g;
}

// ---------------------------------------------------------------------------
// Kernel 2: mono_term[b] = sum_k wlin[k] * x[b,k] * mean_s G_k(x[b,k]*t_s)
// Thread per (b,k); 16-lane shuffle reduce over k.
// ---------------------------------------------------------------------------
__global__ void __launch_bounds__(256) mono_kernel(
    const float* __restrict__ X, const float* __restrict__ wlin)
{
    int gid = blockIdx.x * 256 + threadIdx.x;
    int b = gid >> 4;
    int k = gid & 15;

    float x = __ldg(X + b * INF + k);
    const float* tk = g_tab + k * NT;
    const float scale = (float)(NT - 1) / (2.f * PMAXF);

    float acc = 0.f;
#pragma unroll
    for (int s = 0; s < SQ; s++) {
        float t = (float)s * (1.f / (SQ - 1));
        float f = (x * t + PMAXF) * scale;
        f = fminf(fmaxf(f, 0.f), (float)(NT - 1) - 1e-3f);
        int i0 = (int)f;
        float fr = f - (float)i0;
        float g0 = tk[i0];
        float g1 = tk[i0 + 1];
        acc += fmaf(fr, g1 - g0, g0);
    }
    float part = acc * (1.f / SQ) * x * __ldg(wlin + k);
#pragma unroll
    for (int off = 8; off; off >>= 1)
        part += __shfl_down_sync(0xffffffffu, part, off, 16);
    if (k == 0) g_mono[b] = part;
}

// ---------------------------------------------------------------------------
// Kernel 3: fused non-mono MLP + final add.
// Block = 32 rows, 256 threads (8 warps). Warp w owns rows r0..r0+3 (r0=4w),
// lane owns 4 consecutive cols per 128-col chunk. a1 staged in dynamic smem.
// Layer-3 dot + bias + mono fused into epilogue (warp shuffle reduce).
// ---------------------------------------------------------------------------
__global__ void __launch_bounds__(256) mlp_kernel(
    const float* __restrict__ X,
    const float* __restrict__ w1, const float* __restrict__ b1,
    const float* __restrict__ w2, const float* __restrict__ b2,
    const float* __restrict__ w3, const float* __restrict__ b3,
    float* __restrict__ out)
{
    extern __shared__ float sm[];
    float* xs  = sm;                  // [32][NMD]
    float* a1s = sm + 32 * NMD;       // [32][NH]

    int b0 = blockIdx.x * 32;

    for (int idx = threadIdx.x; idx < 32 * NMD; idx += 256) {
        int r = idx / NMD, i = idx % NMD;
        xs[idx] = X[(b0 + r) * INF + KM + i];
    }
    __syncthreads();

    int rg   = threadIdx.x >> 5;
    int lane = threadIdx.x & 31;
    int r0   = rg * 4;

    // ---- layer 1: a1 = relu(x_nm @ w1 + b1) ----
    for (int chunk = 0; chunk < 4; chunk++) {
        int c0 = chunk * 128 + lane * 4;
        float acc[4][4];
#pragma unroll
        for (int rr = 0; rr < 4; rr++)
#pragma unroll
            for (int cc = 0; cc < 4; cc++) acc[rr][cc] = 0.f;

#pragma unroll 4
        for (int i = 0; i < NMD; i++) {
            float4 w = *(const float4*)(w1 + i * NH + c0);
#pragma unroll
            for (int rr = 0; rr < 4; rr++) {
                float a = xs[(r0 + rr) * NMD + i];
                acc[rr][0] = fmaf(a, w.x, acc[rr][0]);
                acc[rr][1] = fmaf(a, w.y, acc[rr][1]);
                acc[rr][2] = fmaf(a, w.z, acc[rr][2]);
                acc[rr][3] = fmaf(a, w.w, acc[rr][3]);
            }
        }
        float4 bias = *(const float4*)(b1 + c0);
#pragma unroll
        for (int rr = 0; rr < 4; rr++) {
            float4 v;
            v.x = fmaxf(acc[rr][0] + bias.x, 0.f);
            v.y = fmaxf(acc[rr][1] + bias.y, 0.f);
            v.z = fmaxf(acc[rr][2] + bias.z, 0.f);
            v.w = fmaxf(acc[rr][3] + bias.w, 0.f);
            *(float4*)(a1s + (r0 + rr) * NH + c0) = v;
        }
    }
    __syncthreads();

    // ---- layer 2 + layer 3 fused ----
    float p3[4] = {0.f, 0.f, 0.f, 0.f};

    for (int chunk = 0; chunk < 4; chunk++) {
        int c0 = chunk * 128 + lane * 4;
        float acc[4][4];
#pragma unroll
        for (int rr = 0; rr < 4; rr++)
#pragma unroll
            for (int cc = 0; cc < 4; cc++) acc[rr][cc] = 0.f;

#pragma unroll 4
        for (int i = 0; i < NH; i++) {
            float4 w = *(const float4*)(w2 + i * NH + c0);
#pragma unroll
            for (int rr = 0; rr < 4; rr++) {
                float a = a1s[(r0 + rr) * NH + i];
                acc[rr][0] = fmaf(a, w.x, acc[rr][0]);
                acc[rr][1] = fmaf(a, w.y, acc[rr][1]);
                acc[rr][2] = fmaf(a, w.z, acc[rr][2]);
                acc[rr][3] = fmaf(a, w.w, acc[rr][3]);
            }
        }
        float4 bb = *(const float4*)(b2 + c0);
        float4 ww = *(const float4*)(w3 + c0);   // nw3 is (512,1) contiguous
#pragma unroll
        for (int rr = 0; rr < 4; rr++) {
            p3[rr] = fmaf(fmaxf(acc[rr][0] + bb.x, 0.f), ww.x, p3[rr]);
            p3[rr] = fmaf(fmaxf(acc[rr][1] + bb.y, 0.f), ww.y, p3[rr]);
            p3[rr] = fmaf(fmaxf(acc[rr][2] + bb.z, 0.f), ww.z, p3[rr]);
            p3[rr] = fmaf(fmaxf(acc[rr][3] + bb.w, 0.f), ww.w, p3[rr]);
        }
    }

    // warp-reduce the 512-col partials (all 32 lanes of this warp share rows r0..r0+3)
#pragma unroll
    for (int rr = 0; rr < 4; rr++) {
#pragma unroll
        for (int off = 16; off; off >>= 1)
            p3[rr] += __shfl_down_sync(0xffffffffu, p3[rr], off);
    }
    if (lane == 0) {
        float bias3 = __ldg(b3);
#pragma unroll
        for (int rr = 0; rr < 4; rr++)
            out[b0 + r0 + rr] = p3[rr] + bias3 + g_mono[b0 + r0 + rr];
    }
}

// ---------------------------------------------------------------------------
extern "C" void kernel_launch(void* const* d_in, const int* in_sizes, int n_in,
                              void* d_out, int out_size)
{
    const float* x    = (const float*)d_in[0];
    const float* mw1  = (const float*)d_in[1];
    const float* mb1  = (const float*)d_in[2];
    const float* mw2  = (const float*)d_in[3];
    const float* mb2  = (const float*)d_in[4];
    const float* mw3  = (const float*)d_in[5];
    const float* mb3  = (const float*)d_in[6];
    const float* wlin = (const float*)d_in[7];
    const float* nw1  = (const float*)d_in[8];
    const float* nb1  = (const float*)d_in[9];
    const float* nw2  = (const float*)d_in[10];
    const float* nb2  = (const float*)d_in[11];
    const float* nw3  = (const float*)d_in[12];
    const float* nb3  = (const float*)d_in[13];
    float* out = (float*)d_out;

    int smem = (32 * NMD + 32 * NH) * (int)sizeof(float);  // 71680 B
    cudaFuncSetAttribute(mlp_kernel, cudaFuncAttributeMaxDynamicSharedMemorySize, smem);

    build_tab_kernel<<<KM * 4, 256>>>(mw1, mb1, mw2, mb2, mw3, mb3);
    mono_kernel<<<(B_ * KM) / 256, 256>>>(x, wlin);
    mlp_kernel<<<B_ / 32, 256, smem>>>(x, nw1, nb1, nw2, nb2, nw3, nb3, out);
}

// round 2
// speedup vs baseline: 1.7607x; 1.7607x over previous
#include <cuda_runtime.h>
#include <math.h>

#define B_    4096
#define INF   64
#define KM    16
#define SQ    32
#define HH    64
#define NMD   48
#define NH    512
#define NT    1024
#define PMAXF 8.0f

// a1s transposed layout stride (floats per column record); 36*4=144 bytes, 16B aligned
#define TSTR  36

// Scratch (no allocations allowed)
__device__ float g_tab[KM * NT];   // G_k(p) tables

// ---------------------------------------------------------------------------
// f32x2 helpers (Blackwell packed fp32 SIMD2)
// ---------------------------------------------------------------------------
__device__ __forceinline__ unsigned long long pack2(float lo, float hi) {
    unsigned long long r;
    asm("mov.b64 %0, {%1, %2};" : "=l"(r) : "f"(lo), "f"(hi));
    return r;
}
__device__ __forceinline__ float2 unpack2(unsigned long long v) {
    float2 r;
    asm("mov.b64 {%0, %1}, %2;" : "=f"(r.x), "=f"(r.y) : "l"(v));
    return r;
}
__device__ __forceinline__ void fma2(unsigned long long& d,
                                     unsigned long long a,
                                     unsigned long long b) {
    asm("fma.rn.f32x2 %0, %1, %2, %0;" : "+l"(d) : "l"(a), "l"(b));
}

// ---------------------------------------------------------------------------
// Kernel 1: tabulate G_k(p). 128 blocks (8 per k) x 128 threads.
// s_w2 read as float4 (4 j-columns at once) -> LDS count /4, 4 indep FMA chains.
// ---------------------------------------------------------------------------
__global__ void __launch_bounds__(128) build_tab_kernel(
    const float* __restrict__ mw1, const float* __restrict__ mb1,
    const float* __restrict__ mw2, const float* __restrict__ mb2,
    const float* __restrict__ mw3, const float* __restrict__ mb3)
{
    __shared__ float s_w2[HH * HH];
    __shared__ float s_w1[HH], s_b1[HH], s_b2[HH], s_w3[HH];

    int k = blockIdx.x >> 3;
    int i = (blockIdx.x & 7) * 128 + threadIdx.x;   // 0..NT-1

    {
        const float4* src = (const float4*)(mw2 + k * HH * HH);
        float4* dst = (float4*)s_w2;
        for (int idx = threadIdx.x; idx < HH * HH / 4; idx += 128)
            dst[idx] = src[idx];
    }
    if (threadIdx.x < HH) {
        s_w1[threadIdx.x] = mw1[k * HH + threadIdx.x];
        s_b1[threadIdx.x] = mb1[k * HH + threadIdx.x];
        s_b2[threadIdx.x] = mb2[k * HH + threadIdx.x];
        s_w3[threadIdx.x] = mw3[k * HH + threadIdx.x];
    }
    __syncthreads();

    float p = -PMAXF + (2.f * PMAXF / (NT - 1)) * (float)i;

    float h1v[HH];
#pragma unroll
    for (int h = 0; h < HH; h++)
        h1v[h] = tanhf(fmaf(p, s_w1[h], s_b1[h]));

    float z = __ldg(mb3 + k);
#pragma unroll 2
    for (int jg = 0; jg < HH / 4; jg++) {
        float4 acc = *(const float4*)&s_b2[jg * 4];
#pragma unroll
        for (int h = 0; h < HH; h++) {
            float4 w = *(const float4*)&s_w2[h * HH + jg * 4];
            float a = h1v[h];
            acc.x = fmaf(a, w.x, acc.x);
            acc.y = fmaf(a, w.y, acc.y);
            acc.z = fmaf(a, w.z, acc.z);
            acc.w = fmaf(a, w.w, acc.w);
        }
        z = fmaf(s_w3[jg * 4 + 0], tanhf(acc.x), z);
        z = fmaf(s_w3[jg * 4 + 1], tanhf(acc.y), z);
        z = fmaf(s_w3[jg * 4 + 2], tanhf(acc.z), z);
        z = fmaf(s_w3[jg * 4 + 3], tanhf(acc.w), z);
    }
    float g = fmaxf(z, 0.f) + log1pf(expf(-fabsf(z)));
    g_tab[k * NT + i] = g;
}

// ---------------------------------------------------------------------------
// Kernel 2: fused mono-lookup + 3-layer MLP + output.
// Block = 32 rows, 256 threads (8 warps). Warp w owns output cols
// [w*64, w*64+64) for ALL 32 rows (disjoint w2 slices -> no L1 redundancy).
// Lane owns 2 adjacent cols; accumulators are f32x2 row-pairs (32 packs/lane).
// a1 stored transposed in smem: a1s[col][row] so row-pairs are LDS.128-able.
// ---------------------------------------------------------------------------
__global__ void __launch_bounds__(256) fused_kernel(
    const float* __restrict__ X,    const float* __restrict__ wlin,
    const float* __restrict__ w1,   const float* __restrict__ b1,
    const float* __restrict__ w2,   const float* __restrict__ b2,
    const float* __restrict__ w3,   const float* __restrict__ b3,
    float* __restrict__ out)
{
    extern __shared__ float sm[];
    float* xs     = sm;                            // [NMD][TSTR]  transposed x_nm
    float* a1s    = xs + NMD * TSTR;               // [NH][TSTR]   transposed a1
    float* wpart  = a1s + NH * TSTR;               // [8][32]      per-warp row partials
    float* mono_s = wpart + 8 * 32;                // [32]

    const int tid  = threadIdx.x;
    const int warp = tid >> 5;
    const int lane = tid & 31;
    const int b0   = blockIdx.x * 32;
    const int c0   = warp * 64 + lane * 2;         // this lane's 2 output cols

    // ---- stage x_nm transposed: xs[i][r] ----
    for (int idx = tid; idx < 32 * NMD; idx += 256) {
        int r = idx / NMD, i = idx % NMD;
        xs[i * TSTR + r] = X[(b0 + r) * INF + KM + i];
    }

    // ---- mono term: 8 threads per row, 2 k each, width-8 shuffle reduce ----
    {
        int r  = tid >> 3;
        int kb = (tid & 7) * 2;
        const float scale = (float)(NT - 1) / (2.f * PMAXF);
        float part = 0.f;
#pragma unroll
        for (int kk = 0; kk < 2; kk++) {
            int k = kb + kk;
            float x = __ldg(X + (b0 + r) * INF + k);
            const float* tk = g_tab + k * NT;
            float acc = 0.f;
#pragma unroll
            for (int s = 0; s < SQ; s++) {
                float t = (float)s * (1.f / (SQ - 1));
                float f = (x * t + PMAXF) * scale;
                f = fminf(fmaxf(f, 0.f), (float)(NT - 1) - 1e-3f);
                int i0 = (int)f;
                float fr = f - (float)i0;
                float g0 = tk[i0];
                float g1 = tk[i0 + 1];
                acc += fmaf(fr, g1 - g0, g0);
            }
            part += acc * (1.f / SQ) * x * __ldg(wlin + k);
        }
#pragma unroll
        for (int off = 4; off; off >>= 1)
            part += __shfl_down_sync(0xffffffffu, part, off, 8);
        if ((tid & 7) == 0) mono_s[r] = part;
    }
    __syncthreads();

    // ---- layer 1: a1[cols c0,c0+1][all 32 rows] ----
    {
        unsigned long long acc[16][2];
#pragma unroll
        for (int rp = 0; rp < 16; rp++) { acc[rp][0] = 0ull; acc[rp][1] = 0ull; }

        const float* wp = w1 + c0;
#pragma unroll 2
        for (int i = 0; i < NMD; i++) {
            float2 wv = *(const float2*)(wp + i * NH);
            unsigned long long wd0 = pack2(wv.x, wv.x);
            unsigned long long wd1 = pack2(wv.y, wv.y);
            const ulonglong2* ap = (const ulonglong2*)(xs + i * TSTR);
#pragma unroll
            for (int q = 0; q < 8; q++) {
                ulonglong2 a = ap[q];                 // rows 4q..4q+3
                fma2(acc[2 * q][0],     a.x, wd0);
                fma2(acc[2 * q][1],     a.x, wd1);
                fma2(acc[2 * q + 1][0], a.y, wd0);
                fma2(acc[2 * q + 1][1], a.y, wd1);
            }
        }
        float2 bv = *(const float2*)(b1 + c0);
#pragma unroll
        for (int rp = 0; rp < 16; rp++) {
            float2 v0 = unpack2(acc[rp][0]);
            float2 v1 = unpack2(acc[rp][1]);
            a1s[c0 * TSTR + 2 * rp]           = fmaxf(v0.x + bv.x, 0.f);
            a1s[c0 * TSTR + 2 * rp + 1]       = fmaxf(v0.y + bv.x, 0.f);
            a1s[(c0 + 1) * TSTR + 2 * rp]     = fmaxf(v1.x + bv.y, 0.f);
            a1s[(c0 + 1) * TSTR + 2 * rp + 1] = fmaxf(v1.y + bv.y, 0.f);
        }
    }
    __syncthreads();

    // ---- layer 2 (+ fused layer-3 dot in epilogue) ----
    {
        unsigned long long acc[16][2];
#pragma unroll
        for (int rp = 0; rp < 16; rp++) { acc[rp][0] = 0ull; acc[rp][1] = 0ull; }

        const float* wp = w2 + c0;
#pragma unroll 2
        for (int i = 0; i < NH; i++) {
            float2 wv = *(const float2*)(wp + i * NH);
            unsigned long long wd0 = pack2(wv.x, wv.x);
            unsigned long long wd1 = pack2(wv.y, wv.y);
            const ulonglong2* ap = (const ulonglong2*)(a1s + i * TSTR);
#pragma unroll
            for (int q = 0; q < 8; q++) {
                ulonglong2 a = ap[q];
                fma2(acc[2 * q][0],     a.x, wd0);
                fma2(acc[2 * q][1],     a.x, wd1);
                fma2(acc[2 * q + 1][0], a.y, wd0);
                fma2(acc[2 * q + 1][1], a.y, wd1);
            }
        }

        // epilogue: relu(acc + b2) . w3  -> per-row partial for this 64-col slice
        float2 b2v = *(const float2*)(b2 + c0);
        float2 w3v = *(const float2*)(w3 + c0);
#pragma unroll
        for (int rp = 0; rp < 16; rp++) {
            float2 v0 = unpack2(acc[rp][0]);   // col c0,   rows (2rp, 2rp+1)
            float2 v1 = unpack2(acc[rp][1]);   // col c0+1
            float plo = fmaf(fmaxf(v0.x + b2v.x, 0.f), w3v.x,
                             fmaxf(v1.x + b2v.y, 0.f) * w3v.y);
            float phi = fmaf(fmaxf(v0.y + b2v.x, 0.f), w3v.x,
                             fmaxf(v1.y + b2v.y, 0.f) * w3v.y);
#pragma unroll
            for (int off = 16; off; off >>= 1) {
                plo += __shfl_down_sync(0xffffffffu, plo, off);
                phi += __shfl_down_sync(0xffffffffu, phi, off);
            }
            if (lane == 0) {
                wpart[warp * 32 + 2 * rp]     = plo;
                wpart[warp * 32 + 2 * rp + 1] = phi;
            }
        }
    }
    __syncthreads();

    // ---- final: sum 8 warp slices + bias + mono ----
    if (tid < 32) {
        float s = 0.f;
#pragma unroll
        for (int w = 0; w < 8; w++) s += wpart[w * 32 + tid];
        out[b0 + tid] = s + __ldg(b3) + mono_s[tid];
    }
}

// ---------------------------------------------------------------------------
extern "C" void kernel_launch(void* const* d_in, const int* in_sizes, int n_in,
                              void* d_out, int out_size)
{
    const float* x    = (const float*)d_in[0];
    const float* mw1  = (const float*)d_in[1];
    const float* mb1  = (const float*)d_in[2];
    const float* mw2  = (const float*)d_in[3];
    const float* mb2  = (const float*)d_in[4];
    const float* mw3  = (const float*)d_in[5];
    const float* mb3  = (const float*)d_in[6];
    const float* wlin = (const float*)d_in[7];
    const float* nw1  = (const float*)d_in[8];
    const float* nb1  = (const float*)d_in[9];
    const float* nw2  = (const float*)d_in[10];
    const float* nb2  = (const float*)d_in[11];
    const float* nw3  = (const float*)d_in[12];
    const float* nb3  = (const float*)d_in[13];
    float* out = (float*)d_out;

    int smem = (NMD * TSTR + NH * TSTR + 8 * 32 + 32) * (int)sizeof(float);  // ~81.8 KB
    cudaFuncSetAttribute(fused_kernel, cudaFuncAttributeMaxDynamicSharedMemorySize, smem);

    build_tab_kernel<<<KM * 8, 128>>>(mw1, mb1, mw2, mb2, mw3, mb3);
    fused_kernel<<<B_ / 32, 256, smem>>>(x, wlin, nw1, nb1, nw2, nb2, nw3, nb3, out);
}

// round 3
// speedup vs baseline: 2.3231x; 1.3194x over previous
#include <cuda_runtime.h>
#include <math.h>

#define B_    4096
#define INF   64
#define KM    16
#define SQ    32
#define HH    64
#define NMD   48
#define NH    512
#define NT    1024
#define PMAXF 8.0f

#define ROWS  16          // batch rows per block
#define RSTR  20          // transposed smem stride (16 rows + 4 pad), 80B = 16B-aligned

// Scratch (no allocations allowed)
__device__ float g_tab[KM * NT];   // G_k(p) tables

// ---------------------------------------------------------------------------
// f32x2 helpers (Blackwell packed fp32 SIMD2)
// ---------------------------------------------------------------------------
__device__ __forceinline__ unsigned long long pack2(float lo, float hi) {
    unsigned long long r;
    asm("mov.b64 %0, {%1, %2};" : "=l"(r) : "f"(lo), "f"(hi));
    return r;
}
__device__ __forceinline__ float2 unpack2(unsigned long long v) {
    float2 r;
    asm("mov.b64 {%0, %1}, %2;" : "=f"(r.x), "=f"(r.y) : "l"(v));
    return r;
}
__device__ __forceinline__ void fma2(unsigned long long& d,
                                     unsigned long long a,
                                     unsigned long long b) {
    asm("fma.rn.f32x2 %0, %1, %2, %0;" : "+l"(d) : "l"(a), "l"(b));
}

// ---------------------------------------------------------------------------
// Kernel 1: tabulate G_k(p). 128 blocks (8 per k) x 128 threads.
// ---------------------------------------------------------------------------
__global__ void __launch_bounds__(128) build_tab_kernel(
    const float* __restrict__ mw1, const float* __restrict__ mb1,
    const float* __restrict__ mw2, const float* __restrict__ mb2,
    const float* __restrict__ mw3, const float* __restrict__ mb3)
{
    __shared__ float s_w2[HH * HH];
    __shared__ float s_w1[HH], s_b1[HH], s_b2[HH], s_w3[HH];

    int k = blockIdx.x >> 3;
    int i = (blockIdx.x & 7) * 128 + threadIdx.x;   // 0..NT-1

    {
        const float4* src = (const float4*)(mw2 + k * HH * HH);
        float4* dst = (float4*)s_w2;
        for (int idx = threadIdx.x; idx < HH * HH / 4; idx += 128)
            dst[idx] = src[idx];
    }
    if (threadIdx.x < HH) {
        s_w1[threadIdx.x] = mw1[k * HH + threadIdx.x];
        s_b1[threadIdx.x] = mb1[k * HH + threadIdx.x];
        s_b2[threadIdx.x] = mb2[k * HH + threadIdx.x];
        s_w3[threadIdx.x] = mw3[k * HH + threadIdx.x];
    }
    __syncthreads();

    float p = -PMAXF + (2.f * PMAXF / (NT - 1)) * (float)i;

    float h1v[HH];
#pragma unroll
    for (int h = 0; h < HH; h++)
        h1v[h] = tanhf(fmaf(p, s_w1[h], s_b1[h]));

    float z = __ldg(mb3 + k);
#pragma unroll 2
    for (int jg = 0; jg < HH / 4; jg++) {
        float4 acc = *(const float4*)&s_b2[jg * 4];
#pragma unroll
        for (int h = 0; h < HH; h++) {
            float4 w = *(const float4*)&s_w2[h * HH + jg * 4];
            float a = h1v[h];
            acc.x = fmaf(a, w.x, acc.x);
            acc.y = fmaf(a, w.y, acc.y);
            acc.z = fmaf(a, w.z, acc.z);
            acc.w = fmaf(a, w.w, acc.w);
        }
        z = fmaf(s_w3[jg * 4 + 0], tanhf(acc.x), z);
        z = fmaf(s_w3[jg * 4 + 1], tanhf(acc.y), z);
        z = fmaf(s_w3[jg * 4 + 2], tanhf(acc.z), z);
        z = fmaf(s_w3[jg * 4 + 3], tanhf(acc.w), z);
    }
    float g = fmaxf(z, 0.f) + log1pf(expf(-fabsf(z)));
    g_tab[k * NT + i] = g;
}

// ---------------------------------------------------------------------------
// Kernel 2: fused mono-lookup + 3-layer MLP + output.
// Block = 16 rows, 256 threads (8 warps), 2 blocks/SM. Warp w owns output
// cols [w*64, w*64+64) for ALL 16 rows (disjoint w2 slices). Lane owns 2 cols.
// Accumulators: 8 row-pairs x 2 cols of f32x2. W is double-buffered 8 deep in
// registers so 8 LDGs are always in flight (hides L2 latency).
// ---------------------------------------------------------------------------
__global__ void __launch_bounds__(256, 2) fused_kernel(
    const float* __restrict__ X,    const float* __restrict__ wlin,
    const float* __restrict__ w1,   const float* __restrict__ b1,
    const float* __restrict__ w2,   const float* __restrict__ b2,
    const float* __restrict__ w3,   const float* __restrict__ b3,
    float* __restrict__ out)
{
    extern __shared__ float sm[];
    float* xs     = sm;                            // [NMD][RSTR]  transposed x_nm
    float* a1s    = xs + NMD * RSTR;               // [NH][RSTR]   transposed a1
    float* wpart  = a1s + NH * RSTR;               // [8][ROWS]    per-warp row partials
    float* mono_s = wpart + 8 * ROWS;              // [ROWS]

    const int tid  = threadIdx.x;
    const int warp = tid >> 5;
    const int lane = tid & 31;
    const int b0   = blockIdx.x * ROWS;
    const int c0   = warp * 64 + lane * 2;         // this lane's 2 output cols

    // ---- stage x_nm transposed: xs[i][r] ----
    for (int idx = tid; idx < ROWS * NMD; idx += 256) {
        int r = idx / NMD, i = idx % NMD;
        xs[i * RSTR + r] = X[(b0 + r) * INF + KM + i];
    }

    // ---- mono term: one (row, k) per thread, width-16 shuffle reduce ----
    {
        int r = tid >> 4;          // 0..15
        int k = tid & 15;          // 0..15
        const float scale = (float)(NT - 1) / (2.f * PMAXF);
        float x = __ldg(X + (b0 + r) * INF + k);
        const float* tk = g_tab + k * NT;
        float acc = 0.f;
#pragma unroll
        for (int s = 0; s < SQ; s++) {
            float t = (float)s * (1.f / (SQ - 1));
            float f = (x * t + PMAXF) * scale;
            f = fminf(fmaxf(f, 0.f), (float)(NT - 1) - 1e-3f);
            int i0 = (int)f;
            float fr = f - (float)i0;
            float g0 = tk[i0];
            float g1 = tk[i0 + 1];
            acc += fmaf(fr, g1 - g0, g0);
        }
        float part = acc * (1.f / SQ) * x * __ldg(wlin + k);
#pragma unroll
        for (int off = 8; off; off >>= 1)
            part += __shfl_down_sync(0xffffffffu, part, off, 16);
        if ((tid & 15) == 0) mono_s[r] = part;
    }
    __syncthreads();

    // ---- layer 1: a1[cols c0,c0+1][all 16 rows], 6 chunks of 8 i ----
    {
        unsigned long long acc[8][2];
#pragma unroll
        for (int rp = 0; rp < 8; rp++) { acc[rp][0] = 0ull; acc[rp][1] = 0ull; }

        const float* wp = w1 + c0;
        float2 wbuf[2][8];
#pragma unroll
        for (int u = 0; u < 8; u++) wbuf[0][u] = *(const float2*)(wp + u * NH);

#pragma unroll 2
        for (int c = 0; c < NMD / 8; c++) {
            int cur = c & 1, nxt = cur ^ 1;
            if (c + 1 < NMD / 8) {
                const float* wn = wp + (c + 1) * 8 * NH;
#pragma unroll
                for (int u = 0; u < 8; u++) wbuf[nxt][u] = *(const float2*)(wn + u * NH);
            }
            const float* abase = xs + c * 8 * RSTR;
#pragma unroll
            for (int u = 0; u < 8; u++) {
                unsigned long long wd0 = pack2(wbuf[cur][u].x, wbuf[cur][u].x);
                unsigned long long wd1 = pack2(wbuf[cur][u].y, wbuf[cur][u].y);
                const ulonglong2* ap = (const ulonglong2*)(abase + u * RSTR);
#pragma unroll
                for (int q = 0; q < 4; q++) {
                    ulonglong2 a = ap[q];
                    fma2(acc[2 * q][0],     a.x, wd0);
                    fma2(acc[2 * q][1],     a.x, wd1);
                    fma2(acc[2 * q + 1][0], a.y, wd0);
                    fma2(acc[2 * q + 1][1], a.y, wd1);
                }
            }
        }
        float2 bv = *(const float2*)(b1 + c0);
#pragma unroll
        for (int rp = 0; rp < 8; rp++) {
            float2 v0 = unpack2(acc[rp][0]);
            float2 v1 = unpack2(acc[rp][1]);
            float2 s0, s1;
            s0.x = fmaxf(v0.x + bv.x, 0.f);
            s0.y = fmaxf(v0.y + bv.x, 0.f);
            s1.x = fmaxf(v1.x + bv.y, 0.f);
            s1.y = fmaxf(v1.y + bv.y, 0.f);
            *(float2*)(a1s + c0 * RSTR + 2 * rp)       = s0;
            *(float2*)(a1s + (c0 + 1) * RSTR + 2 * rp) = s1;
        }
    }
    __syncthreads();

    // ---- layer 2 (+ fused layer-3 dot), 64 chunks of 8 i ----
    {
        unsigned long long acc[8][2];
#pragma unroll
        for (int rp = 0; rp < 8; rp++) { acc[rp][0] = 0ull; acc[rp][1] = 0ull; }

        const float* wp = w2 + c0;
        float2 wbuf[2][8];
#pragma unroll
        for (int u = 0; u < 8; u++) wbuf[0][u] = *(const float2*)(wp + u * NH);

#pragma unroll 2
        for (int c = 0; c < NH / 8; c++) {
            int cur = c & 1, nxt = cur ^ 1;
            if (c + 1 < NH / 8) {
                const float* wn = wp + (c + 1) * 8 * NH;
#pragma unroll
                for (int u = 0; u < 8; u++) wbuf[nxt][u] = *(const float2*)(wn + u * NH);
            }
            const float* abase = a1s + c * 8 * RSTR;
#pragma unroll
            for (int u = 0; u < 8; u++) {
                unsigned long long wd0 = pack2(wbuf[cur][u].x, wbuf[cur][u].x);
                unsigned long long wd1 = pack2(wbuf[cur][u].y, wbuf[cur][u].y);
                const ulonglong2* ap = (const ulonglong2*)(abase + u * RSTR);
#pragma unroll
                for (int q = 0; q < 4; q++) {
                    ulonglong2 a = ap[q];
                    fma2(acc[2 * q][0],     a.x, wd0);
                    fma2(acc[2 * q][1],     a.x, wd1);
                    fma2(acc[2 * q + 1][0], a.y, wd0);
                    fma2(acc[2 * q + 1][1], a.y, wd1);
                }
            }
        }

        // epilogue: relu(acc + b2) . w3 -> per-row partial for this 64-col slice
        float2 b2v = *(const float2*)(b2 + c0);
        float2 w3v = *(const float2*)(w3 + c0);
#pragma unroll
        for (int rp = 0; rp < 8; rp++) {
            float2 v0 = unpack2(acc[rp][0]);   // col c0,   rows (2rp, 2rp+1)
            float2 v1 = unpack2(acc[rp][1]);   // col c0+1
            float plo = fmaf(fmaxf(v0.x + b2v.x, 0.f), w3v.x,
                             fmaxf(v1.x + b2v.y, 0.f) * w3v.y);
            float phi = fmaf(fmaxf(v0.y + b2v.x, 0.f), w3v.x,
                             fmaxf(v1.y + b2v.y, 0.f) * w3v.y);
#pragma unroll
            for (int off = 16; off; off >>= 1) {
                plo += __shfl_down_sync(0xffffffffu, plo, off);
                phi += __shfl_down_sync(0xffffffffu, phi, off);
            }
            if (lane == 0) {
                wpart[warp * ROWS + 2 * rp]     = plo;
                wpart[warp * ROWS + 2 * rp + 1] = phi;
            }
        }
    }
    __syncthreads();

    // ---- final: sum 8 warp slices + bias + mono ----
    if (tid < ROWS) {
        float s = 0.f;
#pragma unroll
        for (int w = 0; w < 8; w++) s += wpart[w * ROWS + tid];
        out[b0 + tid] = s + __ldg(b3) + mono_s[tid];
    }
}

// ---------------------------------------------------------------------------
extern "C" void kernel_launch(void* const* d_in, const int* in_sizes, int n_in,
                              void* d_out, int out_size)
{
    const float* x    = (const float*)d_in[0];
    const float* mw1  = (const float*)d_in[1];
    const float* mb1  = (const float*)d_in[2];
    const float* mw2  = (const float*)d_in[3];
    const float* mb2  = (const float*)d_in[4];
    const float* mw3  = (const float*)d_in[5];
    const float* mb3  = (const float*)d_in[6];
    const float* wlin = (const float*)d_in[7];
    const float* nw1  = (const float*)d_in[8];
    const float* nb1  = (const float*)d_in[9];
    const float* nw2  = (const float*)d_in[10];
    const float* nb2  = (const float*)d_in[11];
    const float* nw3  = (const float*)d_in[12];
    const float* nb3  = (const float*)d_in[13];
    float* out = (float*)d_out;

    int smem = (NMD * RSTR + NH * RSTR + 8 * ROWS + ROWS) * (int)sizeof(float);  // ~45.4 KB
    cudaFuncSetAttribute(fused_kernel, cudaFuncAttributeMaxDynamicSharedMemorySize, smem);

    build_tab_kernel<<<KM * 8, 128>>>(mw1, mb1, mw2, mb2, mw3, mb3);
    fused_kernel<<<B_ / ROWS, 256, smem>>>(x, wlin, nw1, nb1, nw2, nb2, nw3, nb3, out);
}